// round 13
// baseline (speedup 1.0000x reference)
#include <cuda_runtime.h>
#include <cuda_fp16.h>
#include <cstdint>

// ---------------- problem constants ----------------
#define S   2048
#define E   1024
#define H   16
#define D   64
#define Bn  2
#define M_ROWS (Bn * S)
#define OUT_N  (Bn * S * E)
#define ATT_N  (134217728)
#define GST 40      // gemm smem row stride (halves), BK=32 + pad
#define KST 72      // fused smem row stride (halves)

// ---------------- device scratch ----------------
__device__ __half g_ah[3u * M_ROWS * E];   // fp16 copies of query,key,value
__device__ __half g_wh[4u * E * E];        // fp16 copies of Wq,Wk,Wv,Wo
__device__ __half g_q[Bn * H * S * D];
__device__ __half g_k[Bn * H * S * D];
__device__ __half g_vt[Bn * H * D * S];    // V transposed: [b,h,d,s]
__device__ __half g_ctx[Bn * S * E];
__device__ float  g_out[OUT_N];
__device__ float  g_attn[ATT_N];

// ---------------- helpers ----------------
__device__ __forceinline__ uint32_t f2h2(float a, float b) {
    __half2 h = __floats2half2_rn(a, b);
    return *(uint32_t*)&h;
}
__device__ __forceinline__ void ldsm4(uint32_t r[4], uint32_t addr) {
    asm volatile("ldmatrix.sync.aligned.m8n8.x4.shared.b16 {%0,%1,%2,%3}, [%4];"
        : "=r"(r[0]), "=r"(r[1]), "=r"(r[2]), "=r"(r[3]) : "r"(addr));
}
__device__ __forceinline__ void mma16(float c[4], const uint32_t a[4],
                                      uint32_t b0, uint32_t b1) {
    asm volatile("mma.sync.aligned.m16n8k16.row.col.f32.f16.f16.f32 "
        "{%0,%1,%2,%3},{%4,%5,%6,%7},{%8,%9},{%0,%1,%2,%3};"
        : "+f"(c[0]), "+f"(c[1]), "+f"(c[2]), "+f"(c[3])
        : "r"(a[0]), "r"(a[1]), "r"(a[2]), "r"(a[3]), "r"(b0), "r"(b1));
}
__device__ __forceinline__ void cpa16(uint32_t dst, const void* src) {
    asm volatile("cp.async.ca.shared.global [%0], [%1], 16;" :: "r"(dst), "l"(src));
}
__device__ __forceinline__ void cp_commit() {
    asm volatile("cp.async.commit_group;");
}
__device__ __forceinline__ void cp_wait0() {
    asm volatile("cp.async.wait_group 0;");
}
__device__ __forceinline__ void cp_wait1() {
    asm volatile("cp.async.wait_group 1;");
}
__device__ __forceinline__ void cp_wait2() {
    asm volatile("cp.async.wait_group 2;");
}

// ============================================================
// fp32 -> fp16 conversion, z selects tensor (8 elems/thread)
// ============================================================
struct CvtArgs {
    const float* src[7];
    __half*      dst[7];
    int          n[7];
};
__global__ __launch_bounds__(256) void cvt_f2h(CvtArgs a)
{
    const int z = blockIdx.z;
    const int i = (blockIdx.x * 256 + threadIdx.x) * 8;
    if (i >= a.n[z]) return;
    const float4 f0 = *(const float4*)(a.src[z] + i);
    const float4 f1 = *(const float4*)(a.src[z] + i + 4);
    uint4 u;
    u.x = f2h2(f0.x, f0.y); u.y = f2h2(f0.z, f0.w);
    u.z = f2h2(f1.x, f1.y); u.w = f2h2(f1.z, f1.w);
    *(uint4*)(a.dst[z] + i) = u;
}

// ============================================================
// GEMM: out = A[M,K] @ W[N,K]^T + bias  (fp16, 3-stage cp.async)
// dynamic smem: A stages [0, 3*stageB), W stages [3*stageB, 6*stageB)
// ============================================================
extern __shared__ char dsm[];

__global__ __launch_bounds__(256, 2) void gemm_h(
    const __half* A0, const __half* A1, const __half* A2,
    const __half* W0, const __half* W1, const __half* W2,
    const float* b0p, const float* b1p, const float* b2p,
    void* o0, void* o1, void* o2,
    int m0, int m1, int m2, int K)
{
    const int z = blockIdx.z;
    const __half* A    = (z == 0) ? A0 : (z == 1) ? A1 : A2;
    const __half* W    = (z == 0) ? W0 : (z == 1) ? W1 : W2;
    const float*  bias = (z == 0) ? b0p : (z == 1) ? b1p : b2p;
    void*         outv = (z == 0) ? o0 : (z == 1) ? o1 : o2;
    const int     mode = (z == 0) ? m0 : (z == 1) ? m1 : m2;

    const uint32_t stageB = 128 * GST * 2;          // bytes per stage
    const uint32_t sA = (uint32_t)__cvta_generic_to_shared(dsm);
    const uint32_t sW = sA + 3 * stageB;

    const int tid = threadIdx.x, lane = tid & 31, warp = tid >> 5;
    const int rowBase = blockIdx.y * 128, colBase = blockIdx.x * 128;

    float acc[4][4][4];
#pragma unroll
    for (int i = 0; i < 4; i++)
#pragma unroll
        for (int j = 0; j < 4; j++)
#pragma unroll
            for (int l = 0; l < 4; l++) acc[i][j][l] = 0.f;

    const int wm = warp & 1, wn = warp >> 1;
    const uint32_t aOff = ((wm * 64 + (lane & 7) + ((lane >> 3) & 1) * 8) * GST
                          + (lane >> 4) * 8) * 2;
    const uint32_t bOff = ((wn * 32 + (lane & 7) + (lane >> 4) * 8) * GST
                          + ((lane >> 3) & 1) * 8) * 2;

    auto stage_cp = [&](int buf, int k0) {
#pragma unroll
        for (int t = 0; t < 2; t++) {
            const int c = tid + t * 256;
            const int r = c >> 2, h8 = (c & 3) * 8;
            cpa16(sA + buf * stageB + (r * GST + h8) * 2,
                  A + (size_t)(rowBase + r) * K + k0 + h8);
            cpa16(sW + buf * stageB + (r * GST + h8) * 2,
                  W + (size_t)(colBase + r) * K + k0 + h8);
        }
    };

    const int NT = K >> 5;                 // 32-deep k tiles
    stage_cp(0, 0);  cp_commit();
    stage_cp(1, 32); cp_commit();

    for (int i = 0; i < NT; i++) {
        if (i + 1 < NT) cp_wait1(); else cp_wait0();
        __syncthreads();
        if (i + 2 < NT) { stage_cp((i + 2) % 3, (i + 2) * 32); cp_commit(); }
        const int cur = i % 3;
#pragma unroll
        for (int ks = 0; ks < 2; ks++) {
            uint32_t bF[2][4];
#pragma unroll
            for (int np = 0; np < 2; np++)
                ldsm4(bF[np], sW + cur * stageB + bOff + np * (16 * GST * 2) + ks * 32);
#pragma unroll
            for (int mt = 0; mt < 4; mt++) {
                uint32_t aF[4];
                ldsm4(aF, sA + cur * stageB + aOff + mt * (16 * GST * 2) + ks * 32);
#pragma unroll
                for (int nt = 0; nt < 4; nt++)
                    mma16(acc[mt][nt], aF, bF[nt >> 1][(nt & 1) * 2], bF[nt >> 1][(nt & 1) * 2 + 1]);
            }
        }
    }

    const int gid = lane >> 2, tig = lane & 3;
#pragma unroll
    for (int nt = 0; nt < 4; nt++) {
        const int col0 = colBase + wn * 32 + nt * 8 + tig * 2;
        const float bb0 = bias[col0], bb1 = bias[col0 + 1];
#pragma unroll
        for (int mt = 0; mt < 4; mt++) {
            const int row0 = rowBase + wm * 64 + mt * 16 + gid;
            const float v00 = acc[mt][nt][0] + bb0, v01 = acc[mt][nt][1] + bb1;
            const float v10 = acc[mt][nt][2] + bb0, v11 = acc[mt][nt][3] + bb1;
            if (mode == 0) {
                float* out = (float*)outv;
                *(float2*)&out[(size_t)row0 * E + col0]       = make_float2(v00, v01);
                *(float2*)&out[(size_t)(row0 + 8) * E + col0] = make_float2(v10, v11);
            } else if (mode == 1) {
                __half* out = (__half*)outv;
                const int b = row0 >> 11, s0 = row0 & (S - 1);
                const int h = col0 >> 6, d0 = col0 & 63;
                const size_t base = ((size_t)(b * H + h)) * S;
                *(uint32_t*)&out[(base + s0) * D + d0]     = f2h2(v00, v01);
                *(uint32_t*)&out[(base + s0 + 8) * D + d0] = f2h2(v10, v11);
            } else {
                __half* out = (__half*)outv;
                const int b = row0 >> 11, s0 = row0 & (S - 1);
                const int h = col0 >> 6, d0 = col0 & 63;
                const size_t base = ((size_t)(b * H + h)) * D;
                out[(base + d0) * S + s0]         = __float2half_rn(v00);
                out[(base + d0 + 1) * S + s0]     = __float2half_rn(v01);
                out[(base + d0) * S + s0 + 8]     = __float2half_rn(v10);
                out[(base + d0 + 1) * S + s0 + 8] = __float2half_rn(v11);
            }
        }
    }
}

// ============================================================
// Fused attention (fp16): register P, 3-stage K/V rings.
// ============================================================
__global__ __launch_bounds__(256, 2) void fused_attn(
    const __half* __restrict__ q, const __half* __restrict__ k,
    const __half* __restrict__ vt, float* __restrict__ attn,
    __half* __restrict__ ctx)
{
    const int bh = blockIdx.x;
    const int it = 15 - blockIdx.y;
    const int nj = 2 * (it + 1);
    const int tid = threadIdx.x, lane = tid & 31, w = tid >> 5;
    const int gid = lane >> 2, tig = lane & 3;

    __half* QP = (__half*)dsm;              // 128*KST (Q staging)
    __half* Ks = QP + 128 * KST;            // 3 x 64*KST
    __half* Vs = Ks + 3 * 64 * KST;         // 3 x 64*KST

    const uint32_t sQP = (uint32_t)__cvta_generic_to_shared(QP);
    const uint32_t sK  = (uint32_t)__cvta_generic_to_shared(Ks);
    const uint32_t sV  = (uint32_t)__cvta_generic_to_shared(Vs);
    const uint32_t bufB = 64 * KST * 2;

    const __half* qbase = q + ((size_t)bh * S + (size_t)it * 128) * D;
    const __half* kbase = k + (size_t)bh * S * D;
    const __half* vbase = vt + (size_t)bh * D * S;

    const uint32_t aAddr = sQP + ((w * 16 + (lane & 7) + ((lane >> 3) & 1) * 8) * KST
                                  + (lane >> 4) * 8) * 2;
    const uint32_t bOff = (((lane & 7) + (lane >> 4) * 8) * KST
                           + ((lane >> 3) & 1) * 8) * 2;

    auto k_cp = [&](int buf, int jt) {
#pragma unroll
        for (int t = 0; t < 2; t++) {
            const int c = tid + t * 256;
            const int r = c >> 3, c8 = (c & 7) * 8;
            cpa16(sK + buf * bufB + (r * KST + c8) * 2,
                  kbase + (size_t)(jt * 64 + r) * 64 + c8);
        }
    };
    auto v_cp = [&](int buf, int jt) {
#pragma unroll
        for (int t = 0; t < 2; t++) {
            const int c = tid + t * 256;
            const int r = c >> 3, c8 = (c & 7) * 8;
            cpa16(sV + buf * bufB + (r * KST + c8) * 2,
                  vbase + (size_t)r * S + jt * 64 + c8);
        }
    };

    // ---- prologue: Q group, K0, K1 ----
#pragma unroll
    for (int t = 0; t < 4; t++) {
        const int c = tid + t * 256;
        const int r = c >> 3, c8 = (c & 7) * 8;
        cpa16(sQP + (r * KST + c8) * 2, qbase + r * 64 + c8);
    }
    cp_commit();
    k_cp(0, 0); cp_commit();
    k_cp(1, 1); cp_commit();

    cp_wait2();                             // Q landed
    __syncthreads();
    uint32_t aQ[4][4];
#pragma unroll
    for (int kc = 0; kc < 4; kc++) ldsm4(aQ[kc], aAddr + kc * 32);

    float as[8][4];
    float Zacc[2] = {0.f, 0.f};

    // =================== PASS 1: Z (warp-local) ===================
    for (int jt = 0; jt < nj; jt++) {
        if (jt + 1 < nj) cp_wait1(); else cp_wait0();
        __syncthreads();
        if (jt + 2 < nj) { k_cp((jt + 2) % 3, jt + 2); cp_commit(); }
        const uint32_t kb = sK + (jt % 3) * bufB + bOff;
#pragma unroll
        for (int nt = 0; nt < 8; nt++)
#pragma unroll
            for (int c = 0; c < 4; c++) as[nt][c] = 0.f;
#pragma unroll
        for (int kp = 0; kp < 4; kp++) {
#pragma unroll
            for (int np = 0; np < 4; np++) {
                uint32_t bF[4];
                ldsm4(bF, kb + np * (16 * KST * 2) + kp * 32);
                mma16(as[np * 2],     aQ[kp], bF[0], bF[1]);
                mma16(as[np * 2 + 1], aQ[kp], bF[2], bF[3]);
            }
        }
        const bool diag = (jt >= 2 * it);
#pragma unroll
        for (int h = 0; h < 2; h++) {
            const int li = it * 128 + w * 16 + gid + h * 8;
            float z = 0.f;
#pragma unroll
            for (int nt = 0; nt < 8; nt++) {
                const int lj = jt * 64 + nt * 8 + tig * 2;
                float e0 = __expf(as[nt][h * 2]     * 0.125f);
                float e1 = __expf(as[nt][h * 2 + 1] * 0.125f);
                if (diag) { if (lj > li) e0 = 0.f; if (lj + 1 > li) e1 = 0.f; }
                z += e0 + e1;
            }
            Zacc[h] += z;
        }
    }

    float Zi[2];
#pragma unroll
    for (int h = 0; h < 2; h++) {
        float z = Zacc[h];
        z += __shfl_xor_sync(0xffffffffu, z, 1);
        z += __shfl_xor_sync(0xffffffffu, z, 2);
        Zi[h] = 1.f / z;
    }

    // =================== PASS 2: p + P@V (register P) ===================
    __syncthreads();                        // all pass-1 K reads done
    k_cp(0, 0); v_cp(0, 0); cp_commit();
    k_cp(1, 1); v_cp(1, 1); cp_commit();

    float cacc[8][4];
#pragma unroll
    for (int nt = 0; nt < 8; nt++)
#pragma unroll
        for (int c = 0; c < 4; c++) cacc[nt][c] = 0.f;

    const int gi0 = it * 128 + w * 16 + gid;

    for (int jt = 0; jt < nj; jt++) {
        if (jt + 1 < nj) cp_wait1(); else cp_wait0();
        __syncthreads();
        if (jt + 2 < nj) { k_cp((jt + 2) % 3, jt + 2); v_cp((jt + 2) % 3, jt + 2); cp_commit(); }
        const uint32_t kb = sK + (jt % 3) * bufB + bOff;
        const uint32_t vb = sV + (jt % 3) * bufB + bOff;
#pragma unroll
        for (int nt = 0; nt < 8; nt++)
#pragma unroll
            for (int c = 0; c < 4; c++) as[nt][c] = 0.f;
#pragma unroll
        for (int kp = 0; kp < 4; kp++) {
#pragma unroll
            for (int np = 0; np < 4; np++) {
                uint32_t bF[4];
                ldsm4(bF, kb + np * (16 * KST * 2) + kp * 32);
                mma16(as[np * 2],     aQ[kp], bF[0], bF[1]);
                mma16(as[np * 2 + 1], aQ[kp], bF[2], bF[3]);
            }
        }
        // p = exp(s)/Z : write fp32 attn + pack fp16 A-fragments in regs
        const bool diag = (jt >= 2 * it);
        uint32_t pk[8][2];
        float* prow0 = attn + ((size_t)bh * S + gi0) * S + jt * 64;
        float* prow1 = prow0 + (size_t)8 * S;
#pragma unroll
        for (int nt = 0; nt < 8; nt++) {
            const int lj = jt * 64 + nt * 8 + tig * 2;
            float p0 = __expf(as[nt][0] * 0.125f) * Zi[0];
            float p1 = __expf(as[nt][1] * 0.125f) * Zi[0];
            float p2 = __expf(as[nt][2] * 0.125f) * Zi[1];
            float p3 = __expf(as[nt][3] * 0.125f) * Zi[1];
            if (diag) {
                if (lj > gi0)         p0 = 0.f;
                if (lj + 1 > gi0)     p1 = 0.f;
                if (lj > gi0 + 8)     p2 = 0.f;
                if (lj + 1 > gi0 + 8) p3 = 0.f;
            }
            *(float2*)(prow0 + nt * 8 + tig * 2) = make_float2(p0, p1);
            *(float2*)(prow1 + nt * 8 + tig * 2) = make_float2(p2, p3);
            pk[nt][0] = f2h2(p0, p1);
            pk[nt][1] = f2h2(p2, p3);
        }

        // ctx += P(16x64) @ V(64x64), P straight from registers
#pragma unroll
        for (int kp = 0; kp < 4; kp++) {
            const uint32_t aP[4] = { pk[2 * kp][0], pk[2 * kp][1],
                                     pk[2 * kp + 1][0], pk[2 * kp + 1][1] };
#pragma unroll
            for (int np = 0; np < 4; np++) {
                uint32_t bF[4];
                ldsm4(bF, vb + np * (16 * KST * 2) + kp * 32);
                mma16(cacc[np * 2],     aP, bF[0], bF[1]);
                mma16(cacc[np * 2 + 1], aP, bF[2], bF[3]);
            }
        }
    }

    // ctx epilogue: fp16 [b,s,h,d] == [M,E]
    const int b = bh >> 4, hh = bh & 15;
#pragma unroll
    for (int nt = 0; nt < 8; nt++) {
        const int d0 = nt * 8 + tig * 2;
        *(uint32_t*)&ctx[((size_t)(b * S + gi0)) * E + hh * D + d0] =
            f2h2(cacc[nt][0], cacc[nt][1]);
        *(uint32_t*)&ctx[((size_t)(b * S + gi0 + 8)) * E + hh * D + d0] =
            f2h2(cacc[nt][2], cacc[nt][3]);
    }

    // zero-fill columns beyond the causal edge
    const int zc0 = nj * 64;
    if (zc0 < S) {
        const int r = tid >> 1;
        float* row = attn + ((size_t)bh * S + it * 128 + r) * S;
        const float4 z = make_float4(0.f, 0.f, 0.f, 0.f);
        for (int c = zc0 + (tid & 1) * 4; c < S; c += 8)
            *(float4*)(row + c) = z;
    }
}

// ============================================================
// launch
// ============================================================
extern "C" void kernel_launch(void* const* d_in, const int* in_sizes, int n_in,
                              void* d_out_v, int out_size)
{
    const float* query = (const float*)d_in[0];
    const float* key_  = (const float*)d_in[1];
    const float* value = (const float*)d_in[2];
    const float* Wq = (const float*)d_in[4];
    const float* bq = (const float*)d_in[5];
    const float* Wk = (const float*)d_in[6];
    const float* bk = (const float*)d_in[7];
    const float* Wv = (const float*)d_in[8];
    const float* bv = (const float*)d_in[9];
    const float* Wo = (const float*)d_in[10];
    const float* bo = (const float*)d_in[11];
    float* d_out = (float*)d_out_v;

    __half *ahp, *whp, *qp, *kp, *vtp, *cp;
    float *op, *ap;
    cudaGetSymbolAddress((void**)&ahp, g_ah);
    cudaGetSymbolAddress((void**)&whp, g_wh);
    cudaGetSymbolAddress((void**)&qp,  g_q);
    cudaGetSymbolAddress((void**)&kp,  g_k);
    cudaGetSymbolAddress((void**)&vtp, g_vt);
    cudaGetSymbolAddress((void**)&cp,  g_ctx);
    cudaGetSymbolAddress((void**)&op,  g_out);
    cudaGetSymbolAddress((void**)&ap,  g_attn);

    float* out_ptr;
    float* attn_ptr;
    long long osz = (long long)out_size;
    if (osz >= (long long)OUT_N + (long long)ATT_N) {
        out_ptr = d_out; attn_ptr = d_out + OUT_N;
    } else if (osz == (long long)OUT_N) {
        out_ptr = d_out; attn_ptr = ap;
    } else {
        attn_ptr = d_out; out_ptr = op;
    }

    const int GEMM_SMEM  = 6 * 128 * GST * 2;                // 61440 B
    const int FUSED_SMEM = (128 * KST + 6 * 64 * KST) * 2;   // 73728 B
    cudaFuncSetAttribute(gemm_h, cudaFuncAttributeMaxDynamicSharedMemorySize,
                         GEMM_SMEM);
    cudaFuncSetAttribute(fused_attn, cudaFuncAttributeMaxDynamicSharedMemorySize,
                         FUSED_SMEM);

    const int NA = M_ROWS * E;
    const int NW = E * E;
    __half* ah0 = ahp;
    __half* ah1 = ahp + (size_t)NA;
    __half* ah2 = ahp + (size_t)2 * NA;
    __half* wq = whp;
    __half* wk = whp + (size_t)NW;
    __half* wv = whp + (size_t)2 * NW;
    __half* wo = whp + (size_t)3 * NW;

    CvtArgs ca;
    ca.src[0] = query; ca.src[1] = key_; ca.src[2] = value;
    ca.src[3] = Wq; ca.src[4] = Wk; ca.src[5] = Wv; ca.src[6] = Wo;
    ca.dst[0] = ah0; ca.dst[1] = ah1; ca.dst[2] = ah2;
    ca.dst[3] = wq; ca.dst[4] = wk; ca.dst[5] = wv; ca.dst[6] = wo;
    ca.n[0] = ca.n[1] = ca.n[2] = NA;
    ca.n[3] = ca.n[4] = ca.n[5] = ca.n[6] = NW;
    cvt_f2h<<<dim3(NA / 8 / 256, 1, 7), 256>>>(ca);

    gemm_h<<<dim3(E / 128, M_ROWS / 128, 3), 256, GEMM_SMEM>>>(
        ah0, ah1, ah2, wq, wk, wv, bq, bk, bv,
        qp, kp, vtp, 1, 1, 2, E);

    dim3 gF(Bn * H, 16);
    fused_attn<<<gF, 256, FUSED_SMEM>>>(qp, kp, vtp, attn_ptr, cp);

    gemm_h<<<dim3(E / 128, M_ROWS / 128, 1), 256, GEMM_SMEM>>>(
        cp, cp, cp, wo, wo, wo, bo, bo, bo,
        out_ptr, out_ptr, out_ptr, 0, 0, 0, E);
}

// round 14
// speedup vs baseline: 1.0308x; 1.0308x over previous
#include <cuda_runtime.h>
#include <cuda_fp16.h>
#include <cstdint>

// ---------------- problem constants ----------------
#define S   2048
#define E   1024
#define H   16
#define D   64
#define Bn  2
#define M_ROWS (Bn * S)
#define OUT_N  (Bn * S * E)
#define ATT_N  (134217728)
#define GST 40      // gemm smem row stride (halves), BK=32 + pad
#define KST 72      // fused smem row stride (halves)

// ---------------- device scratch ----------------
__device__ __half g_ah[3u * M_ROWS * E];   // fp16 copies of query,key,value
__device__ __half g_wh[4u * E * E];        // fp16 copies of Wq,Wk,Wv,Wo
__device__ __half g_q[Bn * H * S * D];
__device__ __half g_k[Bn * H * S * D];
__device__ __half g_vt[Bn * H * D * S];    // V transposed: [b,h,d,s]
__device__ __half g_ctx[Bn * S * E];
__device__ float  g_out[OUT_N];
__device__ float  g_attn[ATT_N];

// ---------------- helpers ----------------
__device__ __forceinline__ uint32_t f2h2(float a, float b) {
    __half2 h = __floats2half2_rn(a, b);
    return *(uint32_t*)&h;
}
__device__ __forceinline__ void ldsm4(uint32_t r[4], uint32_t addr) {
    asm volatile("ldmatrix.sync.aligned.m8n8.x4.shared.b16 {%0,%1,%2,%3}, [%4];"
        : "=r"(r[0]), "=r"(r[1]), "=r"(r[2]), "=r"(r[3]) : "r"(addr));
}
__device__ __forceinline__ void mma16(float c[4], const uint32_t a[4],
                                      uint32_t b0, uint32_t b1) {
    asm volatile("mma.sync.aligned.m16n8k16.row.col.f32.f16.f16.f32 "
        "{%0,%1,%2,%3},{%4,%5,%6,%7},{%8,%9},{%0,%1,%2,%3};"
        : "+f"(c[0]), "+f"(c[1]), "+f"(c[2]), "+f"(c[3])
        : "r"(a[0]), "r"(a[1]), "r"(a[2]), "r"(a[3]), "r"(b0), "r"(b1));
}
__device__ __forceinline__ void cpa16(uint32_t dst, const void* src) {
    asm volatile("cp.async.ca.shared.global [%0], [%1], 16;" :: "r"(dst), "l"(src));
}
__device__ __forceinline__ void cp_commit() {
    asm volatile("cp.async.commit_group;");
}
__device__ __forceinline__ void cp_wait0() {
    asm volatile("cp.async.wait_group 0;");
}
__device__ __forceinline__ void cp_wait2() {
    asm volatile("cp.async.wait_group 2;");
}

// ============================================================
// fp32 -> fp16 conversion, z selects tensor (8 elems/thread)
// ============================================================
struct CvtArgs {
    const float* src[7];
    __half*      dst[7];
    int          n[7];
};
__global__ __launch_bounds__(256) void cvt_f2h(CvtArgs a)
{
    const int z = blockIdx.z;
    const int i = (blockIdx.x * 256 + threadIdx.x) * 8;
    if (i >= a.n[z]) return;
    const float4 f0 = *(const float4*)(a.src[z] + i);
    const float4 f1 = *(const float4*)(a.src[z] + i + 4);
    uint4 u;
    u.x = f2h2(f0.x, f0.y); u.y = f2h2(f0.z, f0.w);
    u.z = f2h2(f1.x, f1.y); u.w = f2h2(f1.z, f1.w);
    *(uint4*)(a.dst[z] + i) = u;
}

// ============================================================
// GEMM: out = A[M,K] @ W[N,K]^T + bias  (fp16, 2-stage cp.async)
// z = 0..2: GEMM roles; z = 3: attn upper-triangle zero-fill role
// (co-scheduled: DRAM-bound zero blocks overlap tensor-bound GEMM).
// ============================================================
__global__ __launch_bounds__(256, 2) void gemm_h(
    const __half* A0, const __half* A1, const __half* A2,
    const __half* W0, const __half* W1, const __half* W2,
    const float* b0p, const float* b1p, const float* b2p,
    void* o0, void* o1, void* o2,
    int m0, int m1, int m2, int K, float* attnZ)
{
    const int z = blockIdx.z;
    if (z == 3) {
        // zero-fill role: 256 blocks, each owns 2 of 512 (bh, stripe) pairs
        const int q = blockIdx.y * 8 + blockIdx.x;
        const float4 zv = make_float4(0.f, 0.f, 0.f, 0.f);
#pragma unroll
        for (int pp = 0; pp < 2; pp++) {
            const int pair = q + pp * 256;
            const int bh = pair >> 4, it = pair & 15;
            const int colStart = (it + 1) * 128;
            if (colStart >= S) continue;
            const int nC4 = (S - colStart) >> 2;
            float* base = attnZ + ((size_t)bh * S + (size_t)it * 128) * S + colStart;
            for (int r = 0; r < 128; r++) {
                float4* row = (float4*)(base + (size_t)r * S);
                for (int c = threadIdx.x; c < nC4; c += 256)
                    row[c] = zv;
            }
        }
        return;
    }

    const __half* A    = (z == 0) ? A0 : (z == 1) ? A1 : A2;
    const __half* W    = (z == 0) ? W0 : (z == 1) ? W1 : W2;
    const float*  bias = (z == 0) ? b0p : (z == 1) ? b1p : b2p;
    void*         outv = (z == 0) ? o0 : (z == 1) ? o1 : o2;
    const int     mode = (z == 0) ? m0 : (z == 1) ? m1 : m2;

    __shared__ __align__(16) __half As[2][128 * GST];
    __shared__ __align__(16) __half Ws[2][128 * GST];
    const int tid = threadIdx.x, lane = tid & 31, warp = tid >> 5;
    const int rowBase = blockIdx.y * 128, colBase = blockIdx.x * 128;

    float acc[4][4][4];
#pragma unroll
    for (int i = 0; i < 4; i++)
#pragma unroll
        for (int j = 0; j < 4; j++)
#pragma unroll
            for (int l = 0; l < 4; l++) acc[i][j][l] = 0.f;

    const int wm = warp & 1, wn = warp >> 1;
    const uint32_t sA = (uint32_t)__cvta_generic_to_shared(&As[0][0]);
    const uint32_t sW = (uint32_t)__cvta_generic_to_shared(&Ws[0][0]);
    const uint32_t aOff = ((wm * 64 + (lane & 7) + ((lane >> 3) & 1) * 8) * GST
                          + (lane >> 4) * 8) * 2;
    const uint32_t bOff = ((wn * 32 + (lane & 7) + (lane >> 4) * 8) * GST
                          + ((lane >> 3) & 1) * 8) * 2;
    const uint32_t stageB = 128 * GST * 2;

    auto stage_cp = [&](int buf, int k0) {
#pragma unroll
        for (int t = 0; t < 2; t++) {
            const int c = tid + t * 256;
            const int r = c >> 2, h8 = (c & 3) * 8;
            cpa16(sA + buf * stageB + (r * GST + h8) * 2,
                  A + (size_t)(rowBase + r) * K + k0 + h8);
            cpa16(sW + buf * stageB + (r * GST + h8) * 2,
                  W + (size_t)(colBase + r) * K + k0 + h8);
        }
    };

    stage_cp(0, 0);
    cp_commit();
    cp_wait0();
    __syncthreads();

    for (int k0 = 0; k0 < K; k0 += 32) {
        const int cur = (k0 >> 5) & 1;
        const bool more = (k0 + 32 < K);
        if (more) { stage_cp(cur ^ 1, k0 + 32); cp_commit(); }
#pragma unroll
        for (int ks = 0; ks < 2; ks++) {
            uint32_t bF[2][4];
#pragma unroll
            for (int np = 0; np < 2; np++)
                ldsm4(bF[np], sW + cur * stageB + bOff + np * (16 * GST * 2) + ks * 32);
#pragma unroll
            for (int mt = 0; mt < 4; mt++) {
                uint32_t aF[4];
                ldsm4(aF, sA + cur * stageB + aOff + mt * (16 * GST * 2) + ks * 32);
#pragma unroll
                for (int nt = 0; nt < 4; nt++)
                    mma16(acc[mt][nt], aF, bF[nt >> 1][(nt & 1) * 2], bF[nt >> 1][(nt & 1) * 2 + 1]);
            }
        }
        if (more) { cp_wait0(); __syncthreads(); }
    }

    const int gid = lane >> 2, tig = lane & 3;
#pragma unroll
    for (int nt = 0; nt < 4; nt++) {
        const int col0 = colBase + wn * 32 + nt * 8 + tig * 2;
        const float bb0 = bias[col0], bb1 = bias[col0 + 1];
#pragma unroll
        for (int mt = 0; mt < 4; mt++) {
            const int row0 = rowBase + wm * 64 + mt * 16 + gid;
            const float v00 = acc[mt][nt][0] + bb0, v01 = acc[mt][nt][1] + bb1;
            const float v10 = acc[mt][nt][2] + bb0, v11 = acc[mt][nt][3] + bb1;
            if (mode == 0) {
                float* out = (float*)outv;
                *(float2*)&out[(size_t)row0 * E + col0]       = make_float2(v00, v01);
                *(float2*)&out[(size_t)(row0 + 8) * E + col0] = make_float2(v10, v11);
            } else if (mode == 1) {
                __half* out = (__half*)outv;
                const int b = row0 >> 11, s0 = row0 & (S - 1);
                const int h = col0 >> 6, d0 = col0 & 63;
                const size_t base = ((size_t)(b * H + h)) * S;
                *(uint32_t*)&out[(base + s0) * D + d0]     = f2h2(v00, v01);
                *(uint32_t*)&out[(base + s0 + 8) * D + d0] = f2h2(v10, v11);
            } else {
                __half* out = (__half*)outv;
                const int b = row0 >> 11, s0 = row0 & (S - 1);
                const int h = col0 >> 6, d0 = col0 & 63;
                const size_t base = ((size_t)(b * H + h)) * D;
                out[(base + d0) * S + s0]         = __float2half_rn(v00);
                out[(base + d0 + 1) * S + s0]     = __float2half_rn(v01);
                out[(base + d0) * S + s0 + 8]     = __float2half_rn(v10);
                out[(base + d0 + 1) * S + s0 + 8] = __float2half_rn(v11);
            }
        }
    }
}

// ============================================================
// Fused attention (fp16): register P->A fragments, no P smem.
// (round-11 structure; zero-fill tail removed — handled by z=3 blocks)
// ============================================================
extern __shared__ char fsm[];

__global__ __launch_bounds__(256, 2) void fused_attn(
    const __half* __restrict__ q, const __half* __restrict__ k,
    const __half* __restrict__ vt, float* __restrict__ attn,
    __half* __restrict__ ctx)
{
    const int bh = blockIdx.x;
    const int it = 15 - blockIdx.y;
    const int nj = 2 * (it + 1);
    const int tid = threadIdx.x, lane = tid & 31, w = tid >> 5;
    const int gid = lane >> 2, tig = lane & 3;

    __half* QP = (__half*)fsm;              // 128*KST (Q staging)
    __half* Ks = QP + 128 * KST;            // 2 x 64*KST
    __half* Vs = Ks + 2 * 64 * KST;         // 2 x 64*KST

    const uint32_t sQP = (uint32_t)__cvta_generic_to_shared(QP);
    const uint32_t sK  = (uint32_t)__cvta_generic_to_shared(Ks);
    const uint32_t sV  = (uint32_t)__cvta_generic_to_shared(Vs);
    const uint32_t bufB = 64 * KST * 2;

    const __half* qbase = q + ((size_t)bh * S + (size_t)it * 128) * D;
    const __half* kbase = k + (size_t)bh * S * D;
    const __half* vbase = vt + (size_t)bh * D * S;

    const uint32_t aAddr = sQP + ((w * 16 + (lane & 7) + ((lane >> 3) & 1) * 8) * KST
                                  + (lane >> 4) * 8) * 2;
    const uint32_t bOff = (((lane & 7) + (lane >> 4) * 8) * KST
                           + ((lane >> 3) & 1) * 8) * 2;

    // ---- prologue: stage Q, prefetch K0 ----
#pragma unroll
    for (int t = 0; t < 4; t++) {
        const int c = tid + t * 256;
        const int r = c >> 3, c8 = (c & 7) * 8;
        cpa16(sQP + (r * KST + c8) * 2, qbase + r * 64 + c8);
    }
    cp_commit();
#pragma unroll
    for (int t = 0; t < 2; t++) {
        const int c = tid + t * 256;
        const int r = c >> 3, c8 = (c & 7) * 8;
        cpa16(sK + (r * KST + c8) * 2, kbase + (size_t)r * 64 + c8);
    }
    cp_commit();
    cp_wait0();
    __syncthreads();

    uint32_t aQ[4][4];
#pragma unroll
    for (int kc = 0; kc < 4; kc++) ldsm4(aQ[kc], aAddr + kc * 32);
    __syncthreads();

    float as[8][4];
    float Zacc[2] = {0.f, 0.f};

    // =================== PASS 1: Z (warp-local) ===================
    for (int jt = 0; jt < nj; jt++) {
        const uint32_t kb = sK + (jt & 1) * bufB + bOff;
        if (jt + 1 < nj) {
#pragma unroll
            for (int t = 0; t < 2; t++) {
                const int c = tid + t * 256;
                const int r = c >> 3, c8 = (c & 7) * 8;
                cpa16(sK + ((jt + 1) & 1) * bufB + (r * KST + c8) * 2,
                      kbase + (size_t)((jt + 1) * 64 + r) * 64 + c8);
            }
            cp_commit();
        }
#pragma unroll
        for (int nt = 0; nt < 8; nt++)
#pragma unroll
            for (int c = 0; c < 4; c++) as[nt][c] = 0.f;
#pragma unroll
        for (int kp = 0; kp < 4; kp++) {
#pragma unroll
            for (int np = 0; np < 4; np++) {
                uint32_t bF[4];
                ldsm4(bF, kb + np * (16 * KST * 2) + kp * 32);
                mma16(as[np * 2],     aQ[kp], bF[0], bF[1]);
                mma16(as[np * 2 + 1], aQ[kp], bF[2], bF[3]);
            }
        }
        const bool diag = (jt >= 2 * it);
#pragma unroll
        for (int h = 0; h < 2; h++) {
            const int li = it * 128 + w * 16 + gid + h * 8;
            float z = 0.f;
#pragma unroll
            for (int nt = 0; nt < 8; nt++) {
                const int lj = jt * 64 + nt * 8 + tig * 2;
                float e0 = __expf(as[nt][h * 2]     * 0.125f);
                float e1 = __expf(as[nt][h * 2 + 1] * 0.125f);
                if (diag) { if (lj > li) e0 = 0.f; if (lj + 1 > li) e1 = 0.f; }
                z += e0 + e1;
            }
            Zacc[h] += z;
        }
        if (jt + 1 < nj) { cp_wait0(); __syncthreads(); }
    }

    float Zi[2];
#pragma unroll
    for (int h = 0; h < 2; h++) {
        float z = Zacc[h];
        z += __shfl_xor_sync(0xffffffffu, z, 1);
        z += __shfl_xor_sync(0xffffffffu, z, 2);
        Zi[h] = 1.f / z;
    }

    // =================== PASS 2: p + P@V (register P) ===================
    __syncthreads();
#pragma unroll
    for (int t = 0; t < 2; t++) {
        const int c = tid + t * 256;
        const int r = c >> 3, c8 = (c & 7) * 8;
        cpa16(sK + (r * KST + c8) * 2, kbase + (size_t)r * 64 + c8);
        cpa16(sV + (r * KST + c8) * 2, vbase + (size_t)r * S + c8);
    }
    cp_commit();
    cp_wait0();
    __syncthreads();

    float cacc[8][4];
#pragma unroll
    for (int nt = 0; nt < 8; nt++)
#pragma unroll
        for (int c = 0; c < 4; c++) cacc[nt][c] = 0.f;

    const int gi0 = it * 128 + w * 16 + gid;

    for (int jt = 0; jt < nj; jt++) {
        const uint32_t kb = sK + (jt & 1) * bufB + bOff;
        const uint32_t vb = sV + (jt & 1) * bufB + bOff;
        if (jt + 1 < nj) {
#pragma unroll
            for (int t = 0; t < 2; t++) {
                const int c = tid + t * 256;
                const int r = c >> 3, c8 = (c & 7) * 8;
                cpa16(sK + ((jt + 1) & 1) * bufB + (r * KST + c8) * 2,
                      kbase + (size_t)((jt + 1) * 64 + r) * 64 + c8);
                cpa16(sV + ((jt + 1) & 1) * bufB + (r * KST + c8) * 2,
                      vbase + (size_t)r * S + (jt + 1) * 64 + c8);
            }
            cp_commit();
        }
#pragma unroll
        for (int nt = 0; nt < 8; nt++)
#pragma unroll
            for (int c = 0; c < 4; c++) as[nt][c] = 0.f;
#pragma unroll
        for (int kp = 0; kp < 4; kp++) {
#pragma unroll
            for (int np = 0; np < 4; np++) {
                uint32_t bF[4];
                ldsm4(bF, kb + np * (16 * KST * 2) + kp * 32);
                mma16(as[np * 2],     aQ[kp], bF[0], bF[1]);
                mma16(as[np * 2 + 1], aQ[kp], bF[2], bF[3]);
            }
        }
        // p = exp(s)/Z : write fp32 attn + pack fp16 A-fragments in regs
        const bool diag = (jt >= 2 * it);
        uint32_t pk[8][2];
        float* prow0 = attn + ((size_t)bh * S + gi0) * S + jt * 64;
        float* prow1 = prow0 + (size_t)8 * S;
#pragma unroll
        for (int nt = 0; nt < 8; nt++) {
            const int lj = jt * 64 + nt * 8 + tig * 2;
            float p0 = __expf(as[nt][0] * 0.125f) * Zi[0];
            float p1 = __expf(as[nt][1] * 0.125f) * Zi[0];
            float p2 = __expf(as[nt][2] * 0.125f) * Zi[1];
            float p3 = __expf(as[nt][3] * 0.125f) * Zi[1];
            if (diag) {
                if (lj > gi0)         p0 = 0.f;
                if (lj + 1 > gi0)     p1 = 0.f;
                if (lj > gi0 + 8)     p2 = 0.f;
                if (lj + 1 > gi0 + 8) p3 = 0.f;
            }
            *(float2*)(prow0 + nt * 8 + tig * 2) = make_float2(p0, p1);
            *(float2*)(prow1 + nt * 8 + tig * 2) = make_float2(p2, p3);
            pk[nt][0] = f2h2(p0, p1);
            pk[nt][1] = f2h2(p2, p3);
        }

        // ctx += P(16x64) @ V(64x64), P straight from registers
#pragma unroll
        for (int kp = 0; kp < 4; kp++) {
            const uint32_t aP[4] = { pk[2 * kp][0], pk[2 * kp][1],
                                     pk[2 * kp + 1][0], pk[2 * kp + 1][1] };
#pragma unroll
            for (int np = 0; np < 4; np++) {
                uint32_t bF[4];
                ldsm4(bF, vb + np * (16 * KST * 2) + kp * 32);
                mma16(cacc[np * 2],     aP, bF[0], bF[1]);
                mma16(cacc[np * 2 + 1], aP, bF[2], bF[3]);
            }
        }
        if (jt + 1 < nj) { cp_wait0(); __syncthreads(); }
    }

    // ctx epilogue: fp16 [b,s,h,d] == [M,E]
    const int b = bh >> 4, hh = bh & 15;
#pragma unroll
    for (int nt = 0; nt < 8; nt++) {
        const int d0 = nt * 8 + tig * 2;
        *(uint32_t*)&ctx[((size_t)(b * S + gi0)) * E + hh * D + d0] =
            f2h2(cacc[nt][0], cacc[nt][1]);
        *(uint32_t*)&ctx[((size_t)(b * S + gi0 + 8)) * E + hh * D + d0] =
            f2h2(cacc[nt][2], cacc[nt][3]);
    }
}

// ============================================================
// launch
// ============================================================
extern "C" void kernel_launch(void* const* d_in, const int* in_sizes, int n_in,
                              void* d_out_v, int out_size)
{
    const float* query = (const float*)d_in[0];
    const float* key_  = (const float*)d_in[1];
    const float* value = (const float*)d_in[2];
    const float* Wq = (const float*)d_in[4];
    const float* bq = (const float*)d_in[5];
    const float* Wk = (const float*)d_in[6];
    const float* bk = (const float*)d_in[7];
    const float* Wv = (const float*)d_in[8];
    const float* bv = (const float*)d_in[9];
    const float* Wo = (const float*)d_in[10];
    const float* bo = (const float*)d_in[11];
    float* d_out = (float*)d_out_v;

    __half *ahp, *whp, *qp, *kp, *vtp, *cp;
    float *op, *ap;
    cudaGetSymbolAddress((void**)&ahp, g_ah);
    cudaGetSymbolAddress((void**)&whp, g_wh);
    cudaGetSymbolAddress((void**)&qp,  g_q);
    cudaGetSymbolAddress((void**)&kp,  g_k);
    cudaGetSymbolAddress((void**)&vtp, g_vt);
    cudaGetSymbolAddress((void**)&cp,  g_ctx);
    cudaGetSymbolAddress((void**)&op,  g_out);
    cudaGetSymbolAddress((void**)&ap,  g_attn);

    float* out_ptr;
    float* attn_ptr;
    long long osz = (long long)out_size;
    if (osz >= (long long)OUT_N + (long long)ATT_N) {
        out_ptr = d_out; attn_ptr = d_out + OUT_N;
    } else if (osz == (long long)OUT_N) {
        out_ptr = d_out; attn_ptr = ap;
    } else {
        attn_ptr = d_out; out_ptr = op;
    }

    const int FUSED_SMEM = (128 * KST + 4 * 64 * KST) * 2;   // 55296 B
    cudaFuncSetAttribute(fused_attn, cudaFuncAttributeMaxDynamicSharedMemorySize,
                         FUSED_SMEM);

    const int NA = M_ROWS * E;
    const int NW = E * E;
    __half* ah0 = ahp;
    __half* ah1 = ahp + (size_t)NA;
    __half* ah2 = ahp + (size_t)2 * NA;
    __half* wq = whp;
    __half* wk = whp + (size_t)NW;
    __half* wv = whp + (size_t)2 * NW;
    __half* wo = whp + (size_t)3 * NW;

    CvtArgs ca;
    ca.src[0] = query; ca.src[1] = key_; ca.src[2] = value;
    ca.src[3] = Wq; ca.src[4] = Wk; ca.src[5] = Wv; ca.src[6] = Wo;
    ca.dst[0] = ah0; ca.dst[1] = ah1; ca.dst[2] = ah2;
    ca.dst[3] = wq; ca.dst[4] = wk; ca.dst[5] = wv; ca.dst[6] = wo;
    ca.n[0] = ca.n[1] = ca.n[2] = NA;
    ca.n[3] = ca.n[4] = ca.n[5] = ca.n[6] = NW;
    cvt_f2h<<<dim3(NA / 8 / 256, 1, 7), 256>>>(ca);

    // merged Q/K/V projections + co-scheduled attn zero-fill (z=3)
    gemm_h<<<dim3(E / 128, M_ROWS / 128, 4), 256>>>(
        ah0, ah1, ah2, wq, wk, wv, bq, bk, bv,
        qp, kp, vtp, 1, 1, 2, E, attn_ptr);

    dim3 gF(Bn * H, 16);
    fused_attn<<<gF, 256, FUSED_SMEM>>>(qp, kp, vtp, attn_ptr, cp);

    // output projection (A = fp16 ctx); z never reaches 3 here
    gemm_h<<<dim3(E / 128, M_ROWS / 128, 1), 256>>>(
        cp, cp, cp, wo, wo, wo, bo, bo, bo,
        out_ptr, out_ptr, out_ptr, 0, 0, 0, E, attn_ptr);
}

// round 15
// speedup vs baseline: 1.0327x; 1.0019x over previous
#include <cuda_runtime.h>
#include <cuda_fp16.h>
#include <cstdint>

// ---------------- problem constants ----------------
#define S   2048
#define E   1024
#define H   16
#define D   64
#define Bn  2
#define M_ROWS (Bn * S)
#define OUT_N  (Bn * S * E)
#define ATT_N  (134217728)
#define GST 40      // gemm smem row stride (halves), BK=32 + pad
#define KST 72      // fused smem row stride (halves)

// ---------------- device scratch ----------------
__device__ __half g_ah[3u * M_ROWS * E];   // fp16 copies of query,key,value
__device__ __half g_wh[4u * E * E];        // fp16 copies of Wq,Wk,Wv,Wo
__device__ __half g_q[Bn * H * S * D];
__device__ __half g_k[Bn * H * S * D];
__device__ __half g_vt[Bn * H * D * S];    // V transposed: [b,h,d,s]
__device__ __half g_ctx[Bn * S * E];
__device__ float  g_out[OUT_N];
__device__ float  g_attn[ATT_N];

// ---------------- helpers ----------------
__device__ __forceinline__ uint32_t f2h2(float a, float b) {
    __half2 h = __floats2half2_rn(a, b);
    return *(uint32_t*)&h;
}
__device__ __forceinline__ void ldsm4(uint32_t r[4], uint32_t addr) {
    asm volatile("ldmatrix.sync.aligned.m8n8.x4.shared.b16 {%0,%1,%2,%3}, [%4];"
        : "=r"(r[0]), "=r"(r[1]), "=r"(r[2]), "=r"(r[3]) : "r"(addr));
}
__device__ __forceinline__ void mma16(float c[4], const uint32_t a[4],
                                      uint32_t b0, uint32_t b1) {
    asm volatile("mma.sync.aligned.m16n8k16.row.col.f32.f16.f16.f32 "
        "{%0,%1,%2,%3},{%4,%5,%6,%7},{%8,%9},{%0,%1,%2,%3};"
        : "+f"(c[0]), "+f"(c[1]), "+f"(c[2]), "+f"(c[3])
        : "r"(a[0]), "r"(a[1]), "r"(a[2]), "r"(a[3]), "r"(b0), "r"(b1));
}
__device__ __forceinline__ void cpa16(uint32_t dst, const void* src) {
    asm volatile("cp.async.ca.shared.global [%0], [%1], 16;" :: "r"(dst), "l"(src));
}
__device__ __forceinline__ void cp_commit() {
    asm volatile("cp.async.commit_group;");
}
__device__ __forceinline__ void cp_wait0() {
    asm volatile("cp.async.wait_group 0;");
}
__device__ __forceinline__ void cp_wait2() {
    asm volatile("cp.async.wait_group 2;");
}

// ============================================================
// fp32 -> fp16 conversion, z selects tensor (8 elems/thread)
// ============================================================
struct CvtArgs {
    const float* src[7];
    __half*      dst[7];
    int          n[7];
};
__global__ __launch_bounds__(256) void cvt_f2h(CvtArgs a)
{
    const int z = blockIdx.z;
    const int i = (blockIdx.x * 256 + threadIdx.x) * 8;
    if (i >= a.n[z]) return;
    const float4 f0 = *(const float4*)(a.src[z] + i);
    const float4 f1 = *(const float4*)(a.src[z] + i + 4);
    uint4 u;
    u.x = f2h2(f0.x, f0.y); u.y = f2h2(f0.z, f0.w);
    u.z = f2h2(f1.x, f1.y); u.w = f2h2(f1.z, f1.w);
    *(uint4*)(a.dst[z] + i) = u;
}

// ============================================================
// GEMM: out = A[M,K] @ W[N,K]^T + bias  (fp16, 2-stage cp.async)
// z = 0..2: GEMM roles; z = 3: attn upper-triangle zero-fill role
// (co-scheduled: DRAM-bound zero blocks overlap tensor-bound GEMM).
// ============================================================
__global__ __launch_bounds__(256, 2) void gemm_h(
    const __half* A0, const __half* A1, const __half* A2,
    const __half* W0, const __half* W1, const __half* W2,
    const float* b0p, const float* b1p, const float* b2p,
    void* o0, void* o1, void* o2,
    int m0, int m1, int m2, int K, float* attnZ)
{
    const int z = blockIdx.z;
    if (z == 3) {
        // zero-fill role: 256 blocks, each owns 2 of 512 (bh, stripe) pairs
        const int q = blockIdx.y * 8 + blockIdx.x;
        const float4 zv = make_float4(0.f, 0.f, 0.f, 0.f);
#pragma unroll
        for (int pp = 0; pp < 2; pp++) {
            const int pair = q + pp * 256;
            const int bh = pair >> 4, it = pair & 15;
            const int colStart = (it + 1) * 128;
            if (colStart >= S) continue;
            const int nC4 = (S - colStart) >> 2;
            float* base = attnZ + ((size_t)bh * S + (size_t)it * 128) * S + colStart;
            for (int r = 0; r < 128; r++) {
                float4* row = (float4*)(base + (size_t)r * S);
                for (int c = threadIdx.x; c < nC4; c += 256)
                    row[c] = zv;
            }
        }
        return;
    }

    const __half* A    = (z == 0) ? A0 : (z == 1) ? A1 : A2;
    const __half* W    = (z == 0) ? W0 : (z == 1) ? W1 : W2;
    const float*  bias = (z == 0) ? b0p : (z == 1) ? b1p : b2p;
    void*         outv = (z == 0) ? o0 : (z == 1) ? o1 : o2;
    const int     mode = (z == 0) ? m0 : (z == 1) ? m1 : m2;

    __shared__ __align__(16) __half As[2][128 * GST];
    __shared__ __align__(16) __half Ws[2][128 * GST];
    const int tid = threadIdx.x, lane = tid & 31, warp = tid >> 5;
    const int rowBase = blockIdx.y * 128, colBase = blockIdx.x * 128;

    float acc[4][4][4];
#pragma unroll
    for (int i = 0; i < 4; i++)
#pragma unroll
        for (int j = 0; j < 4; j++)
#pragma unroll
            for (int l = 0; l < 4; l++) acc[i][j][l] = 0.f;

    const int wm = warp & 1, wn = warp >> 1;
    const uint32_t sA = (uint32_t)__cvta_generic_to_shared(&As[0][0]);
    const uint32_t sW = (uint32_t)__cvta_generic_to_shared(&Ws[0][0]);
    const uint32_t aOff = ((wm * 64 + (lane & 7) + ((lane >> 3) & 1) * 8) * GST
                          + (lane >> 4) * 8) * 2;
    const uint32_t bOff = ((wn * 32 + (lane & 7) + (lane >> 4) * 8) * GST
                          + ((lane >> 3) & 1) * 8) * 2;
    const uint32_t stageB = 128 * GST * 2;

    auto stage_cp = [&](int buf, int k0) {
#pragma unroll
        for (int t = 0; t < 2; t++) {
            const int c = tid + t * 256;
            const int r = c >> 2, h8 = (c & 3) * 8;
            cpa16(sA + buf * stageB + (r * GST + h8) * 2,
                  A + (size_t)(rowBase + r) * K + k0 + h8);
            cpa16(sW + buf * stageB + (r * GST + h8) * 2,
                  W + (size_t)(colBase + r) * K + k0 + h8);
        }
    };

    stage_cp(0, 0);
    cp_commit();
    cp_wait0();
    __syncthreads();

    for (int k0 = 0; k0 < K; k0 += 32) {
        const int cur = (k0 >> 5) & 1;
        const bool more = (k0 + 32 < K);
        if (more) { stage_cp(cur ^ 1, k0 + 32); cp_commit(); }
#pragma unroll
        for (int ks = 0; ks < 2; ks++) {
            uint32_t bF[2][4];
#pragma unroll
            for (int np = 0; np < 2; np++)
                ldsm4(bF[np], sW + cur * stageB + bOff + np * (16 * GST * 2) + ks * 32);
#pragma unroll
            for (int mt = 0; mt < 4; mt++) {
                uint32_t aF[4];
                ldsm4(aF, sA + cur * stageB + aOff + mt * (16 * GST * 2) + ks * 32);
#pragma unroll
                for (int nt = 0; nt < 4; nt++)
                    mma16(acc[mt][nt], aF, bF[nt >> 1][(nt & 1) * 2], bF[nt >> 1][(nt & 1) * 2 + 1]);
            }
        }
        if (more) { cp_wait0(); __syncthreads(); }
    }

    const int gid = lane >> 2, tig = lane & 3;
#pragma unroll
    for (int nt = 0; nt < 4; nt++) {
        const int col0 = colBase + wn * 32 + nt * 8 + tig * 2;
        const float bb0 = bias[col0], bb1 = bias[col0 + 1];
#pragma unroll
        for (int mt = 0; mt < 4; mt++) {
            const int row0 = rowBase + wm * 64 + mt * 16 + gid;
            const float v00 = acc[mt][nt][0] + bb0, v01 = acc[mt][nt][1] + bb1;
            const float v10 = acc[mt][nt][2] + bb0, v11 = acc[mt][nt][3] + bb1;
            if (mode == 0) {
                float* out = (float*)outv;
                *(float2*)&out[(size_t)row0 * E + col0]       = make_float2(v00, v01);
                *(float2*)&out[(size_t)(row0 + 8) * E + col0] = make_float2(v10, v11);
            } else if (mode == 1) {
                __half* out = (__half*)outv;
                const int b = row0 >> 11, s0 = row0 & (S - 1);
                const int h = col0 >> 6, d0 = col0 & 63;
                const size_t base = ((size_t)(b * H + h)) * S;
                *(uint32_t*)&out[(base + s0) * D + d0]     = f2h2(v00, v01);
                *(uint32_t*)&out[(base + s0 + 8) * D + d0] = f2h2(v10, v11);
            } else {
                __half* out = (__half*)outv;
                const int b = row0 >> 11, s0 = row0 & (S - 1);
                const int h = col0 >> 6, d0 = col0 & 63;
                const size_t base = ((size_t)(b * H + h)) * D;
                out[(base + d0) * S + s0]         = __float2half_rn(v00);
                out[(base + d0 + 1) * S + s0]     = __float2half_rn(v01);
                out[(base + d0) * S + s0 + 8]     = __float2half_rn(v10);
                out[(base + d0 + 1) * S + s0 + 8] = __float2half_rn(v11);
            }
        }
    }
}

// ============================================================
// Fused attention (fp16): register P->A fragments, no P smem.
// (round-11 structure; zero-fill tail removed — handled by z=3 blocks)
// ============================================================
extern __shared__ char fsm[];

__global__ __launch_bounds__(256, 2) void fused_attn(
    const __half* __restrict__ q, const __half* __restrict__ k,
    const __half* __restrict__ vt, float* __restrict__ attn,
    __half* __restrict__ ctx)
{
    const int bh = blockIdx.x;
    const int it = 15 - blockIdx.y;
    const int nj = 2 * (it + 1);
    const int tid = threadIdx.x, lane = tid & 31, w = tid >> 5;
    const int gid = lane >> 2, tig = lane & 3;

    __half* QP = (__half*)fsm;              // 128*KST (Q staging)
    __half* Ks = QP + 128 * KST;            // 2 x 64*KST
    __half* Vs = Ks + 2 * 64 * KST;         // 2 x 64*KST

    const uint32_t sQP = (uint32_t)__cvta_generic_to_shared(QP);
    const uint32_t sK  = (uint32_t)__cvta_generic_to_shared(Ks);
    const uint32_t sV  = (uint32_t)__cvta_generic_to_shared(Vs);
    const uint32_t bufB = 64 * KST * 2;

    const __half* qbase = q + ((size_t)bh * S + (size_t)it * 128) * D;
    const __half* kbase = k + (size_t)bh * S * D;
    const __half* vbase = vt + (size_t)bh * D * S;

    const uint32_t aAddr = sQP + ((w * 16 + (lane & 7) + ((lane >> 3) & 1) * 8) * KST
                                  + (lane >> 4) * 8) * 2;
    const uint32_t bOff = (((lane & 7) + (lane >> 4) * 8) * KST
                           + ((lane >> 3) & 1) * 8) * 2;

    // ---- prologue: stage Q, prefetch K0 ----
#pragma unroll
    for (int t = 0; t < 4; t++) {
        const int c = tid + t * 256;
        const int r = c >> 3, c8 = (c & 7) * 8;
        cpa16(sQP + (r * KST + c8) * 2, qbase + r * 64 + c8);
    }
    cp_commit();
#pragma unroll
    for (int t = 0; t < 2; t++) {
        const int c = tid + t * 256;
        const int r = c >> 3, c8 = (c & 7) * 8;
        cpa16(sK + (r * KST + c8) * 2, kbase + (size_t)r * 64 + c8);
    }
    cp_commit();
    cp_wait0();
    __syncthreads();

    uint32_t aQ[4][4];
#pragma unroll
    for (int kc = 0; kc < 4; kc++) ldsm4(aQ[kc], aAddr + kc * 32);
    __syncthreads();

    float as[8][4];
    float Zacc[2] = {0.f, 0.f};

    // =================== PASS 1: Z (warp-local) ===================
    for (int jt = 0; jt < nj; jt++) {
        const uint32_t kb = sK + (jt & 1) * bufB + bOff;
        if (jt + 1 < nj) {
#pragma unroll
            for (int t = 0; t < 2; t++) {
                const int c = tid + t * 256;
                const int r = c >> 3, c8 = (c & 7) * 8;
                cpa16(sK + ((jt + 1) & 1) * bufB + (r * KST + c8) * 2,
                      kbase + (size_t)((jt + 1) * 64 + r) * 64 + c8);
            }
            cp_commit();
        }
#pragma unroll
        for (int nt = 0; nt < 8; nt++)
#pragma unroll
            for (int c = 0; c < 4; c++) as[nt][c] = 0.f;
#pragma unroll
        for (int kp = 0; kp < 4; kp++) {
#pragma unroll
            for (int np = 0; np < 4; np++) {
                uint32_t bF[4];
                ldsm4(bF, kb + np * (16 * KST * 2) + kp * 32);
                mma16(as[np * 2],     aQ[kp], bF[0], bF[1]);
                mma16(as[np * 2 + 1], aQ[kp], bF[2], bF[3]);
            }
        }
        const bool diag = (jt >= 2 * it);
#pragma unroll
        for (int h = 0; h < 2; h++) {
            const int li = it * 128 + w * 16 + gid + h * 8;
            float z = 0.f;
#pragma unroll
            for (int nt = 0; nt < 8; nt++) {
                const int lj = jt * 64 + nt * 8 + tig * 2;
                float e0 = __expf(as[nt][h * 2]     * 0.125f);
                float e1 = __expf(as[nt][h * 2 + 1] * 0.125f);
                if (diag) { if (lj > li) e0 = 0.f; if (lj + 1 > li) e1 = 0.f; }
                z += e0 + e1;
            }
            Zacc[h] += z;
        }
        if (jt + 1 < nj) { cp_wait0(); __syncthreads(); }
    }

    float Zi[2];
#pragma unroll
    for (int h = 0; h < 2; h++) {
        float z = Zacc[h];
        z += __shfl_xor_sync(0xffffffffu, z, 1);
        z += __shfl_xor_sync(0xffffffffu, z, 2);
        Zi[h] = 1.f / z;
    }

    // =================== PASS 2: p + P@V (register P) ===================
    __syncthreads();
#pragma unroll
    for (int t = 0; t < 2; t++) {
        const int c = tid + t * 256;
        const int r = c >> 3, c8 = (c & 7) * 8;
        cpa16(sK + (r * KST + c8) * 2, kbase + (size_t)r * 64 + c8);
        cpa16(sV + (r * KST + c8) * 2, vbase + (size_t)r * S + c8);
    }
    cp_commit();
    cp_wait0();
    __syncthreads();

    float cacc[8][4];
#pragma unroll
    for (int nt = 0; nt < 8; nt++)
#pragma unroll
        for (int c = 0; c < 4; c++) cacc[nt][c] = 0.f;

    const int gi0 = it * 128 + w * 16 + gid;

    for (int jt = 0; jt < nj; jt++) {
        const uint32_t kb = sK + (jt & 1) * bufB + bOff;
        const uint32_t vb = sV + (jt & 1) * bufB + bOff;
        if (jt + 1 < nj) {
#pragma unroll
            for (int t = 0; t < 2; t++) {
                const int c = tid + t * 256;
                const int r = c >> 3, c8 = (c & 7) * 8;
                cpa16(sK + ((jt + 1) & 1) * bufB + (r * KST + c8) * 2,
                      kbase + (size_t)((jt + 1) * 64 + r) * 64 + c8);
                cpa16(sV + ((jt + 1) & 1) * bufB + (r * KST + c8) * 2,
                      vbase + (size_t)r * S + (jt + 1) * 64 + c8);
            }
            cp_commit();
        }
#pragma unroll
        for (int nt = 0; nt < 8; nt++)
#pragma unroll
            for (int c = 0; c < 4; c++) as[nt][c] = 0.f;
#pragma unroll
        for (int kp = 0; kp < 4; kp++) {
#pragma unroll
            for (int np = 0; np < 4; np++) {
                uint32_t bF[4];
                ldsm4(bF, kb + np * (16 * KST * 2) + kp * 32);
                mma16(as[np * 2],     aQ[kp], bF[0], bF[1]);
                mma16(as[np * 2 + 1], aQ[kp], bF[2], bF[3]);
            }
        }
        // p = exp(s)/Z : write fp32 attn + pack fp16 A-fragments in regs
        const bool diag = (jt >= 2 * it);
        uint32_t pk[8][2];
        float* prow0 = attn + ((size_t)bh * S + gi0) * S + jt * 64;
        float* prow1 = prow0 + (size_t)8 * S;
#pragma unroll
        for (int nt = 0; nt < 8; nt++) {
            const int lj = jt * 64 + nt * 8 + tig * 2;
            float p0 = __expf(as[nt][0] * 0.125f) * Zi[0];
            float p1 = __expf(as[nt][1] * 0.125f) * Zi[0];
            float p2 = __expf(as[nt][2] * 0.125f) * Zi[1];
            float p3 = __expf(as[nt][3] * 0.125f) * Zi[1];
            if (diag) {
                if (lj > gi0)         p0 = 0.f;
                if (lj + 1 > gi0)     p1 = 0.f;
                if (lj > gi0 + 8)     p2 = 0.f;
                if (lj + 1 > gi0 + 8) p3 = 0.f;
            }
            *(float2*)(prow0 + nt * 8 + tig * 2) = make_float2(p0, p1);
            *(float2*)(prow1 + nt * 8 + tig * 2) = make_float2(p2, p3);
            pk[nt][0] = f2h2(p0, p1);
            pk[nt][1] = f2h2(p2, p3);
        }

        // ctx += P(16x64) @ V(64x64), P straight from registers
#pragma unroll
        for (int kp = 0; kp < 4; kp++) {
            const uint32_t aP[4] = { pk[2 * kp][0], pk[2 * kp][1],
                                     pk[2 * kp + 1][0], pk[2 * kp + 1][1] };
#pragma unroll
            for (int np = 0; np < 4; np++) {
                uint32_t bF[4];
                ldsm4(bF, vb + np * (16 * KST * 2) + kp * 32);
                mma16(cacc[np * 2],     aP, bF[0], bF[1]);
                mma16(cacc[np * 2 + 1], aP, bF[2], bF[3]);
            }
        }
        if (jt + 1 < nj) { cp_wait0(); __syncthreads(); }
    }

    // ctx epilogue: fp16 [b,s,h,d] == [M,E]
    const int b = bh >> 4, hh = bh & 15;
#pragma unroll
    for (int nt = 0; nt < 8; nt++) {
        const int d0 = nt * 8 + tig * 2;
        *(uint32_t*)&ctx[((size_t)(b * S + gi0)) * E + hh * D + d0] =
            f2h2(cacc[nt][0], cacc[nt][1]);
        *(uint32_t*)&ctx[((size_t)(b * S + gi0 + 8)) * E + hh * D + d0] =
            f2h2(cacc[nt][2], cacc[nt][3]);
    }
}

// ============================================================
// launch
// ============================================================
extern "C" void kernel_launch(void* const* d_in, const int* in_sizes, int n_in,
                              void* d_out_v, int out_size)
{
    const float* query = (const float*)d_in[0];
    const float* key_  = (const float*)d_in[1];
    const float* value = (const float*)d_in[2];
    const float* Wq = (const float*)d_in[4];
    const float* bq = (const float*)d_in[5];
    const float* Wk = (const float*)d_in[6];
    const float* bk = (const float*)d_in[7];
    const float* Wv = (const float*)d_in[8];
    const float* bv = (const float*)d_in[9];
    const float* Wo = (const float*)d_in[10];
    const float* bo = (const float*)d_in[11];
    float* d_out = (float*)d_out_v;

    __half *ahp, *whp, *qp, *kp, *vtp, *cp;
    float *op, *ap;
    cudaGetSymbolAddress((void**)&ahp, g_ah);
    cudaGetSymbolAddress((void**)&whp, g_wh);
    cudaGetSymbolAddress((void**)&qp,  g_q);
    cudaGetSymbolAddress((void**)&kp,  g_k);
    cudaGetSymbolAddress((void**)&vtp, g_vt);
    cudaGetSymbolAddress((void**)&cp,  g_ctx);
    cudaGetSymbolAddress((void**)&op,  g_out);
    cudaGetSymbolAddress((void**)&ap,  g_attn);

    float* out_ptr;
    float* attn_ptr;
    long long osz = (long long)out_size;
    if (osz >= (long long)OUT_N + (long long)ATT_N) {
        out_ptr = d_out; attn_ptr = d_out + OUT_N;
    } else if (osz == (long long)OUT_N) {
        out_ptr = d_out; attn_ptr = ap;
    } else {
        attn_ptr = d_out; out_ptr = op;
    }

    const int FUSED_SMEM = (128 * KST + 4 * 64 * KST) * 2;   // 55296 B
    cudaFuncSetAttribute(fused_attn, cudaFuncAttributeMaxDynamicSharedMemorySize,
                         FUSED_SMEM);

    const int NA = M_ROWS * E;
    const int NW = E * E;
    __half* ah0 = ahp;
    __half* ah1 = ahp + (size_t)NA;
    __half* ah2 = ahp + (size_t)2 * NA;
    __half* wq = whp;
    __half* wk = whp + (size_t)NW;
    __half* wv = whp + (size_t)2 * NW;
    __half* wo = whp + (size_t)3 * NW;

    CvtArgs ca;
    ca.src[0] = query; ca.src[1] = key_; ca.src[2] = value;
    ca.src[3] = Wq; ca.src[4] = Wk; ca.src[5] = Wv; ca.src[6] = Wo;
    ca.dst[0] = ah0; ca.dst[1] = ah1; ca.dst[2] = ah2;
    ca.dst[3] = wq; ca.dst[4] = wk; ca.dst[5] = wv; ca.dst[6] = wo;
    ca.n[0] = ca.n[1] = ca.n[2] = NA;
    ca.n[3] = ca.n[4] = ca.n[5] = ca.n[6] = NW;
    cvt_f2h<<<dim3(NA / 8 / 256, 1, 7), 256>>>(ca);

    // merged Q/K/V projections + co-scheduled attn zero-fill (z=3)
    gemm_h<<<dim3(E / 128, M_ROWS / 128, 4), 256>>>(
        ah0, ah1, ah2, wq, wk, wv, bq, bk, bv,
        qp, kp, vtp, 1, 1, 2, E, attn_ptr);

    dim3 gF(Bn * H, 16);
    fused_attn<<<gF, 256, FUSED_SMEM>>>(qp, kp, vtp, attn_ptr, cp);

    // output projection (A = fp16 ctx); z never reaches 3 here
    gemm_h<<<dim3(E / 128, M_ROWS / 128, 1), 256>>>(
        cp, cp, cp, wo, wo, wo, bo, bo, bo,
        out_ptr, out_ptr, out_ptr, 0, 0, 0, E, attn_ptr);
}